// round 10
// baseline (speedup 1.0000x reference)
#include <cuda_runtime.h>
#include <cstdint>

#define NB     8
#define NVOX   65536
#define GRIDSZ 64
#define G3     (GRIDSZ*GRIDSZ*GRIDSZ)
#define BNTOT  (NB*NVOX)
#define C      16
#define EPSF   1e-3f
#define TILE   1024
#define NTILES (BNTOT/TILE)          // 512
#define NBKT   (NTILES*27)           // 13824
#define ASTR   20                    // acc smem row stride (floats): 8 distinct bank starts

// ---------------- static scratch (no allocation) ----------------
__device__ int   g_idx_map[NB*G3];                 // 8.4 MB
__device__ int   g_pairs[(size_t)NBKT*TILE];       // 56.6 MB: (local<<16)|in_row per (tile,o)
__device__ int   g_cnt[NBKT];
__device__ float g_t0[(size_t)BNTOT*C];            // 33.5 MB pre-BN layer-0
__device__ float g_t1[(size_t)BNTOT*C];            // 33.5 MB pre-BN layer-1
__device__ float g_stats[2*C];                     // [sum16, sumsq16]
__device__ float g_affine[2*C];                    // [A16, B16]

// ---------------- f32x2 helpers ----------------
__device__ __forceinline__ unsigned long long fma2(unsigned long long a,
                                                   unsigned long long b,
                                                   unsigned long long c) {
    unsigned long long d;
    asm("fma.rn.f32x2 %0, %1, %2, %3;" : "=l"(d) : "l"(a), "l"(b), "l"(c));
    return d;
}
__device__ __forceinline__ unsigned long long bcast2(float x) {
    unsigned long long d; unsigned r = __float_as_uint(x);
    asm("mov.b64 %0, {%1, %2};" : "=l"(d) : "r"(r), "r"(r));
    return d;
}

// ---------------- phase 0: hash map ----------------
__global__ void k_init_map() {
    int i = blockIdx.x * blockDim.x + threadIdx.x;
    reinterpret_cast<int4*>(g_idx_map)[i] = make_int4(-1, -1, -1, -1);
}

__global__ void k_scatter(const int* __restrict__ xyz, const int* __restrict__ nv) {
    int bn = blockIdx.x * blockDim.x + threadIdx.x;
    int b = bn >> 16, n = bn & 0xFFFF;
    if (n < nv[b]) {
        const int* c = xyz + (size_t)bn * 3;
        g_idx_map[b * G3 + c[0] * (GRIDSZ*GRIDSZ) + c[1] * GRIDSZ + c[2]] = n;
    }
}

// ---------------- phase 1: per-(tile,o) rulebook ----------------
__global__ __launch_bounds__(1024)
void k_build(const int* __restrict__ xyz, const int* __restrict__ nv) {
    __shared__ int s_cnt[27];
    int tid = threadIdx.x;
    if (tid < 27) s_cnt[tid] = 0;
    __syncthreads();

    int bn = blockIdx.x * TILE + tid;
    int b  = bn >> 16, n = bn & 0xFFFF;
    int tilebase = blockIdx.x * 27;
    if (n < nv[b]) {
        const int* c = xyz + (size_t)bn * 3;
        int x = c[0], y = c[1], z = c[2];
        int base = b * G3;
        #pragma unroll
        for (int o = 0; o < 27; ++o) {
            int dx = o / 9 - 1, dy = (o / 3) % 3 - 1, dz = o % 3 - 1;
            int nx = x + dx, ny = y + dy, nz = z + dz;
            if (((unsigned)nx < GRIDSZ) & ((unsigned)ny < GRIDSZ) & ((unsigned)nz < GRIDSZ)) {
                int idx = g_idx_map[base + nx * (GRIDSZ*GRIDSZ) + ny * GRIDSZ + nz];
                if (idx >= 0) {
                    int pos = atomicAdd(&s_cnt[o], 1);
                    g_pairs[((size_t)(tilebase + o) << 10) + pos] = (tid << 16) | idx;
                }
            }
        }
    }
    __syncthreads();
    if (tid < 27) g_cnt[tilebase + tid] = s_cnt[tid];
}

// ---------------- conv + norm-div + fused BN partial reduce ----------------
// smem floats: acc TILE*ASTR | w 27*256 | nsum TILE | nw 32 | aff 32
#define SM_FLOATS (TILE*ASTR + 27*256 + TILE + 32 + 32)
#define SM_BYTES  (SM_FLOATS * 4)

template<bool AFF>
__global__ __launch_bounds__(256)
void k_conv(const float* __restrict__ feats, const float* __restrict__ w,
            const float* __restrict__ nw, const float* __restrict__ affine,
            float* __restrict__ tout) {
    extern __shared__ float sm[];
    float* s_acc  = sm;
    float* s_w    = sm + TILE*ASTR;
    float* s_nsum = s_w + 27*256;
    float* s_nw   = s_nsum + TILE;
    float* s_aff  = s_nw + 32;

    int tid = threadIdx.x;
    for (int i = tid; i < 27*256; i += 256) s_w[i] = w[i];
    if (tid < 27) s_nw[tid] = nw[tid];
    if (AFF && tid < 32) s_aff[tid] = affine[tid];
    for (int i = tid; i < TILE*ASTR; i += 256) s_acc[i] = 0.0f;
    for (int i = tid; i < TILE;      i += 256) s_nsum[i] = 0.0f;
    __syncthreads();

    int tile = blockIdx.x;
    int b    = tile >> 6;                       // 64 tiles per batch
    const float* fb = feats + (size_t)b * NVOX * C;

    for (int o = 0; o < 27; ++o) {
        int bkt = tile * 27 + o;
        int cnt = g_cnt[bkt];
        const int* pl = g_pairs + ((size_t)bkt << 10);
        float nwo = s_nw[o];
        const ulonglong2* wbase = reinterpret_cast<const ulonglong2*>(s_w + o * 256);

        int idx = tid;
        int p = (idx < cnt) ? pl[idx] : -1;
        while (idx < cnt) {
            int pn = (idx + 256 < cnt) ? pl[idx + 256] : -1;
            int local = p >> 16;
            int row   = p & 0xFFFF;

            const float4* fr = reinterpret_cast<const float4*>(fb + (size_t)row * C);
            float4 fA = __ldg(fr), fB = __ldg(fr+1), fCv = __ldg(fr+2), fD = __ldg(fr+3);
            float fv[16] = { fA.x, fA.y, fA.z, fA.w,  fB.x, fB.y, fB.z, fB.w,
                             fCv.x, fCv.y, fCv.z, fCv.w,  fD.x, fD.y, fD.z, fD.w };
            if (AFF) {
                #pragma unroll
                for (int ci = 0; ci < 16; ++ci)
                    fv[ci] = fmaxf(0.0f, fv[ci] * s_aff[ci] + s_aff[16 + ci]);
            }

            ulonglong2* ap = reinterpret_cast<ulonglong2*>(s_acc + local * ASTR);
            ulonglong2 a01 = ap[0], a23 = ap[1], a45 = ap[2], a67 = ap[3];
            unsigned long long c0=a01.x, c1=a01.y, c2=a23.x, c3=a23.y,
                               c4=a45.x, c5=a45.y, c6=a67.x, c7=a67.y;
            #pragma unroll
            for (int ci = 0; ci < 16; ++ci) {
                unsigned long long a2 = bcast2(fv[ci]);
                ulonglong2 w01 = wbase[ci*4+0], w23 = wbase[ci*4+1],
                           w45 = wbase[ci*4+2], w67 = wbase[ci*4+3];
                c0 = fma2(a2, w01.x, c0);  c1 = fma2(a2, w01.y, c1);
                c2 = fma2(a2, w23.x, c2);  c3 = fma2(a2, w23.y, c3);
                c4 = fma2(a2, w45.x, c4);  c5 = fma2(a2, w45.y, c5);
                c6 = fma2(a2, w67.x, c6);  c7 = fma2(a2, w67.y, c7);
            }
            ap[0] = make_ulonglong2(c0, c1);  ap[1] = make_ulonglong2(c2, c3);
            ap[2] = make_ulonglong2(c4, c5);  ap[3] = make_ulonglong2(c6, c7);
            s_nsum[local] += nwo;

            p = pn; idx += 256;
        }
        __syncthreads();   // o -> o+1 ordering (same out row across o's)
    }

    // epilogue: norm-div, write t, BN partials
    float ps[16], pq[16];
    #pragma unroll
    for (int c2 = 0; c2 < 16; ++c2) { ps[c2] = 0.0f; pq[c2] = 0.0f; }

    #pragma unroll
    for (int k = 0; k < 4; ++k) {
        int i = tid + k * 256;
        float inv = 1.0f / (1.0f + fabsf(s_nsum[i]));
        const float* ar = s_acc + i * ASTR;
        float4* to = reinterpret_cast<float4*>(tout + (size_t)(tile * TILE + i) * C);
        #pragma unroll
        for (int q = 0; q < 4; ++q) {
            float x0 = ar[4*q+0]*inv, x1 = ar[4*q+1]*inv,
                  x2 = ar[4*q+2]*inv, x3 = ar[4*q+3]*inv;
            to[q] = make_float4(x0, x1, x2, x3);
            ps[4*q+0] += x0; pq[4*q+0] += x0*x0;
            ps[4*q+1] += x1; pq[4*q+1] += x1*x1;
            ps[4*q+2] += x2; pq[4*q+2] += x2*x2;
            ps[4*q+3] += x3; pq[4*q+3] += x3*x3;
        }
    }
    #pragma unroll
    for (int off = 16; off; off >>= 1) {
        #pragma unroll
        for (int c2 = 0; c2 < 16; ++c2) {
            ps[c2] += __shfl_xor_sync(0xFFFFFFFFu, ps[c2], off);
            pq[c2] += __shfl_xor_sync(0xFFFFFFFFu, pq[c2], off);
        }
    }
    __syncthreads();                    // everyone done with s_nsum; reuse as reduce stage
    float* s_red = s_nsum;              // 8 warps x 32 floats
    if ((tid & 31) == 0) {
        int wi = tid >> 5;
        #pragma unroll
        for (int c2 = 0; c2 < 16; ++c2) {
            s_red[wi*32 + c2]      = ps[c2];
            s_red[wi*32 + 16 + c2] = pq[c2];
        }
    }
    __syncthreads();
    if (tid < 32) {
        float a = 0.0f;
        #pragma unroll
        for (int wi = 0; wi < 8; ++wi) a += s_red[wi*32 + tid];
        atomicAdd(&g_stats[tid], a);
    }
}

// ---------------- BN finalize (also zeroes stats for next layer/replay) ----------------
__global__ void k_zero_stats() {
    if (threadIdx.x < 2*C) g_stats[threadIdx.x] = 0.0f;
}

__global__ void k_finalize(const float* __restrict__ gamma,
                           const float* __restrict__ beta,
                           const int* __restrict__ nv) {
    int i = threadIdx.x;   // 32 threads
    float A = 0.0f, Bv = 0.0f;
    if (i < C) {
        float cnt = 0.0f;
        #pragma unroll
        for (int b = 0; b < NB; ++b) cnt += (float)nv[b];
        float mean = g_stats[i] / cnt;
        float var  = g_stats[C + i] / cnt - mean * mean;
        A  = rsqrtf(var + EPSF) * gamma[i];
        Bv = beta[i] - mean * A;
    }
    __syncwarp();
    if (i < C) { g_affine[i] = A; g_affine[C + i] = Bv; }
    g_stats[i] = 0.0f;
}

// ---------------- final affine+relu+mask ----------------
__global__ __launch_bounds__(256)
void k_apply(const float* __restrict__ t, const int* __restrict__ nv,
             float* __restrict__ out) {
    __shared__ float sA[32];
    if (threadIdx.x < 32) sA[threadIdx.x] = g_affine[threadIdx.x];
    __syncthreads();
    int bn = blockIdx.x * 256 + threadIdx.x;
    int b = bn >> 16, n = bn & 0xFFFF;
    float4* po = reinterpret_cast<float4*>(out + (size_t)bn * C);
    if (n < nv[b]) {
        const float4* r = reinterpret_cast<const float4*>(t + (size_t)bn * C);
        #pragma unroll
        for (int k = 0; k < 4; ++k) {
            float4 v = r[k];
            float4 y;
            y.x = fmaxf(0.0f, v.x * sA[4*k+0] + sA[16+4*k+0]);
            y.y = fmaxf(0.0f, v.y * sA[4*k+1] + sA[16+4*k+1]);
            y.z = fmaxf(0.0f, v.z * sA[4*k+2] + sA[16+4*k+2]);
            y.w = fmaxf(0.0f, v.w * sA[4*k+3] + sA[16+4*k+3]);
            po[k] = y;
        }
    } else {
        float4 z = make_float4(0.f, 0.f, 0.f, 0.f);
        #pragma unroll
        for (int k = 0; k < 4; ++k) po[k] = z;
    }
}

// ---------------- launch ----------------
extern "C" void kernel_launch(void* const* d_in, const int* in_sizes, int n_in,
                              void* d_out, int out_size) {
    const float* feats = (const float*)d_in[0];
    const int*   xyz   = (const int*)  d_in[1];
    const int*   nv    = (const int*)  d_in[2];
    const float* w0    = (const float*)d_in[3];
    const float* w1    = (const float*)d_in[4];
    const float* nw0   = (const float*)d_in[5];
    const float* nw1   = (const float*)d_in[6];
    const float* ga0   = (const float*)d_in[7];
    const float* be0   = (const float*)d_in[8];
    const float* ga1   = (const float*)d_in[9];
    const float* be1   = (const float*)d_in[10];
    float* out = (float*)d_out;

    float *t0, *t1, *aff;
    cudaGetSymbolAddress((void**)&t0,  g_t0);
    cudaGetSymbolAddress((void**)&t1,  g_t1);
    cudaGetSymbolAddress((void**)&aff, g_affine);

    cudaFuncSetAttribute(k_conv<false>, cudaFuncAttributeMaxDynamicSharedMemorySize, SM_BYTES);
    cudaFuncSetAttribute(k_conv<true>,  cudaFuncAttributeMaxDynamicSharedMemorySize, SM_BYTES);

    k_init_map<<<(NB*G3/4)/256, 256>>>();
    k_scatter <<<BNTOT/256, 256>>>(xyz, nv);
    k_build   <<<NTILES, 1024>>>(xyz, nv);

    k_zero_stats<<<1, 32>>>();

    // layer 0: conv raw feats -> t0 (pre-BN), fused BN partials
    k_conv<false><<<NTILES, 256, SM_BYTES>>>(feats, w0, nw0, nullptr, t0);
    k_finalize<<<1, 32>>>(ga0, be0, nv);

    // layer 1: conv reads t0 applying affine0+relu on gather -> t1 (pre-BN)
    k_conv<true><<<NTILES, 256, SM_BYTES>>>(t0, w1, nw1, aff, t1);
    k_finalize<<<1, 32>>>(ga1, be1, nv);

    k_apply<<<BNTOT/256, 256>>>(t1, nv, out);
}

// round 11
// speedup vs baseline: 1.0143x; 1.0143x over previous
#include <cuda_runtime.h>
#include <cstdint>

#define NB     8
#define NVOX   65536
#define GRIDSZ 64
#define G3     (GRIDSZ*GRIDSZ*GRIDSZ)
#define BNTOT  (NB*NVOX)
#define C      16
#define EPSF   1e-3f
#define TILE   1024
#define NTILES (BNTOT/TILE)          // 512
#define NBKT   (NTILES*27)           // 13824
#define ASTR   20                    // acc smem row stride (16B-aligned, 8 bank-start groups)

// ---------------- static scratch (no allocation) ----------------
__device__ int   g_idx_map[NB*G3];                 // 8.4 MB
__device__ int   g_pairs[(size_t)NBKT*TILE];       // 56.6 MB: (local<<16)|in_row per (tile,o)
__device__ int   g_cnt[NBKT];
__device__ float g_t0[(size_t)BNTOT*C];            // 33.5 MB pre-BN layer-0
__device__ float g_t1[(size_t)BNTOT*C];            // 33.5 MB pre-BN layer-1
__device__ float g_stats[2*C];                     // [sum16, sumsq16] (zeroed by finalize)
__device__ float g_affine[2*C];                    // [A16, B16]

// ---------------- f32x2 helpers ----------------
__device__ __forceinline__ unsigned long long fma2(unsigned long long a,
                                                   unsigned long long b,
                                                   unsigned long long c) {
    unsigned long long d;
    asm("fma.rn.f32x2 %0, %1, %2, %3;" : "=l"(d) : "l"(a), "l"(b), "l"(c));
    return d;
}
__device__ __forceinline__ unsigned long long bcast2(float x) {
    unsigned long long d; unsigned r = __float_as_uint(x);
    asm("mov.b64 %0, {%1, %2};" : "=l"(d) : "r"(r), "r"(r));
    return d;
}

// ---------------- phase 0: hash map ----------------
__global__ void k_init_map() {
    int i = blockIdx.x * blockDim.x + threadIdx.x;
    reinterpret_cast<int4*>(g_idx_map)[i] = make_int4(-1, -1, -1, -1);
}

__global__ void k_scatter(const int* __restrict__ xyz, const int* __restrict__ nv) {
    int bn = blockIdx.x * blockDim.x + threadIdx.x;
    int b = bn >> 16, n = bn & 0xFFFF;
    if (n < nv[b]) {
        const int* c = xyz + (size_t)bn * 3;
        g_idx_map[b * G3 + c[0] * (GRIDSZ*GRIDSZ) + c[1] * GRIDSZ + c[2]] = n;
    }
}

// ---------------- phase 1: per-(tile,o) rulebook (warp-aggregated atomics) ----------------
__global__ __launch_bounds__(1024)
void k_build(const int* __restrict__ xyz, const int* __restrict__ nv) {
    __shared__ int s_cnt[27];
    int tid = threadIdx.x;
    if (tid < 27) s_cnt[tid] = 0;
    __syncthreads();

    int bn = blockIdx.x * TILE + tid;
    int b  = bn >> 16, n = bn & 0xFFFF;
    bool valid = n < nv[b];
    int x = 0, y = 0, z = 0, base = b * G3;
    if (valid) {
        const int* c = xyz + (size_t)bn * 3;
        x = c[0]; y = c[1]; z = c[2];
    }
    int tilebase = blockIdx.x * 27;
    int lane = tid & 31;

    #pragma unroll
    for (int o = 0; o < 27; ++o) {
        int dx = o / 9 - 1, dy = (o / 3) % 3 - 1, dz = o % 3 - 1;
        int idx = -1;
        if (valid) {
            int nx = x + dx, ny = y + dy, nz = z + dz;
            if (((unsigned)nx < GRIDSZ) & ((unsigned)ny < GRIDSZ) & ((unsigned)nz < GRIDSZ))
                idx = g_idx_map[base + nx * (GRIDSZ*GRIDSZ) + ny * GRIDSZ + nz];
        }
        unsigned m = __ballot_sync(0xFFFFFFFFu, idx >= 0);
        if (m) {
            int leader = __ffs(m) - 1;
            int basepos = 0;
            if (lane == leader) basepos = atomicAdd(&s_cnt[o], __popc(m));
            basepos = __shfl_sync(0xFFFFFFFFu, basepos, leader);
            if (idx >= 0) {
                int nbefore = __popc(m & ((1u << lane) - 1u));
                g_pairs[((size_t)(tilebase + o) << 10) + basepos + nbefore] = (tid << 16) | idx;
            }
        }
    }
    __syncthreads();
    if (tid < 27) g_cnt[tilebase + tid] = s_cnt[tid];
}

// ---------------- conv + norm-div + fused BN partial reduce ----------------
// smem floats: acc TILE*ASTR | w 27*256 | nsum TILE | nw 32 | aff 32
#define SM_FLOATS (TILE*ASTR + 27*256 + TILE + 32 + 32)
#define SM_BYTES  (SM_FLOATS * 4)

template<bool AFF>
__global__ __launch_bounds__(256, 2)
void k_conv(const float* __restrict__ feats, const float* __restrict__ w,
            const float* __restrict__ nw, const float* __restrict__ affine,
            float* __restrict__ tout) {
    extern __shared__ float sm[];
    float* s_acc  = sm;
    float* s_w    = sm + TILE*ASTR;
    float* s_nsum = s_w + 27*256;
    float* s_nw   = s_nsum + TILE;
    float* s_aff  = s_nw + 32;

    int tid = threadIdx.x;
    for (int i = tid; i < 27*256; i += 256) s_w[i] = w[i];
    if (tid < 27) s_nw[tid] = nw[tid];
    if (AFF && tid < 32) s_aff[tid] = affine[tid];
    for (int i = tid; i < TILE*ASTR; i += 256) s_acc[i] = 0.0f;
    for (int i = tid; i < TILE;      i += 256) s_nsum[i] = 0.0f;
    __syncthreads();

    int tile = blockIdx.x;
    int b    = tile >> 6;                       // 64 tiles per batch
    const float* fb = feats + (size_t)b * NVOX * C;

    for (int o = 0; o < 27; ++o) {
        int bkt = tile * 27 + o;
        int cnt = g_cnt[bkt];
        const int* pl = g_pairs + ((size_t)bkt << 10);
        float nwo = s_nw[o];
        const ulonglong2* wbase = reinterpret_cast<const ulonglong2*>(s_w + o * 256);

        int idx = tid;
        int p0 = 0;
        float4 A0, B0, C0, D0;
        if (idx < cnt) {
            p0 = pl[idx];
            const float4* fr = reinterpret_cast<const float4*>(fb + (size_t)(p0 & 0xFFFF) * C);
            A0 = __ldg(fr); B0 = __ldg(fr+1); C0 = __ldg(fr+2); D0 = __ldg(fr+3);
        }
        while (idx < cnt) {
            int idx1 = idx + 256;
            int p1 = 0;
            float4 A1, B1, C1, D1;
            if (idx1 < cnt) {
                p1 = pl[idx1];
                const float4* fr = reinterpret_cast<const float4*>(fb + (size_t)(p1 & 0xFFFF) * C);
                A1 = __ldg(fr); B1 = __ldg(fr+1); C1 = __ldg(fr+2); D1 = __ldg(fr+3);
            }

            float fv[16] = { A0.x, A0.y, A0.z, A0.w,  B0.x, B0.y, B0.z, B0.w,
                             C0.x, C0.y, C0.z, C0.w,  D0.x, D0.y, D0.z, D0.w };
            if (AFF) {
                #pragma unroll
                for (int ci = 0; ci < 16; ++ci)
                    fv[ci] = fmaxf(0.0f, fv[ci] * s_aff[ci] + s_aff[16 + ci]);
            }

            int local = p0 >> 16;
            ulonglong2* ap = reinterpret_cast<ulonglong2*>(s_acc + local * ASTR);
            ulonglong2 a01 = ap[0], a23 = ap[1], a45 = ap[2], a67 = ap[3];
            unsigned long long c0=a01.x, c1=a01.y, c2=a23.x, c3=a23.y,
                               c4=a45.x, c5=a45.y, c6=a67.x, c7=a67.y;
            #pragma unroll
            for (int ci = 0; ci < 16; ++ci) {
                unsigned long long a2 = bcast2(fv[ci]);
                ulonglong2 w01 = wbase[ci*4+0], w23 = wbase[ci*4+1],
                           w45 = wbase[ci*4+2], w67 = wbase[ci*4+3];
                c0 = fma2(a2, w01.x, c0);  c1 = fma2(a2, w01.y, c1);
                c2 = fma2(a2, w23.x, c2);  c3 = fma2(a2, w23.y, c3);
                c4 = fma2(a2, w45.x, c4);  c5 = fma2(a2, w45.y, c5);
                c6 = fma2(a2, w67.x, c6);  c7 = fma2(a2, w67.y, c7);
            }
            ap[0] = make_ulonglong2(c0, c1);  ap[1] = make_ulonglong2(c2, c3);
            ap[2] = make_ulonglong2(c4, c5);  ap[3] = make_ulonglong2(c6, c7);
            s_nsum[local] += nwo;

            idx = idx1; p0 = p1;
            A0 = A1; B0 = B1; C0 = C1; D0 = D1;
        }
        __syncthreads();   // o -> o+1 ordering (same out row across o's)
    }

    // epilogue: norm-div, write t, BN partials
    float ps[16], pq[16];
    #pragma unroll
    for (int c2 = 0; c2 < 16; ++c2) { ps[c2] = 0.0f; pq[c2] = 0.0f; }

    #pragma unroll
    for (int k = 0; k < 4; ++k) {
        int i = tid + k * 256;
        float inv = 1.0f / (1.0f + fabsf(s_nsum[i]));
        const float* ar = s_acc + i * ASTR;
        float4* to = reinterpret_cast<float4*>(tout + (size_t)(tile * TILE + i) * C);
        #pragma unroll
        for (int q = 0; q < 4; ++q) {
            float x0 = ar[4*q+0]*inv, x1 = ar[4*q+1]*inv,
                  x2 = ar[4*q+2]*inv, x3 = ar[4*q+3]*inv;
            to[q] = make_float4(x0, x1, x2, x3);
            ps[4*q+0] += x0; pq[4*q+0] += x0*x0;
            ps[4*q+1] += x1; pq[4*q+1] += x1*x1;
            ps[4*q+2] += x2; pq[4*q+2] += x2*x2;
            ps[4*q+3] += x3; pq[4*q+3] += x3*x3;
        }
    }
    #pragma unroll
    for (int off = 16; off; off >>= 1) {
        #pragma unroll
        for (int c2 = 0; c2 < 16; ++c2) {
            ps[c2] += __shfl_xor_sync(0xFFFFFFFFu, ps[c2], off);
            pq[c2] += __shfl_xor_sync(0xFFFFFFFFu, pq[c2], off);
        }
    }
    __syncthreads();                    // everyone done with s_nsum; reuse as reduce stage
    float* s_red = s_nsum;              // 8 warps x 32 floats
    if ((tid & 31) == 0) {
        int wi = tid >> 5;
        #pragma unroll
        for (int c2 = 0; c2 < 16; ++c2) {
            s_red[wi*32 + c2]      = ps[c2];
            s_red[wi*32 + 16 + c2] = pq[c2];
        }
    }
    __syncthreads();
    if (tid < 32) {
        float a = 0.0f;
        #pragma unroll
        for (int wi = 0; wi < 8; ++wi) a += s_red[wi*32 + tid];
        atomicAdd(&g_stats[tid], a);
    }
}

// ---------------- BN finalize (reads stats, writes affine, re-zeroes stats) ----------------
__global__ void k_finalize(const float* __restrict__ gamma,
                           const float* __restrict__ beta,
                           const int* __restrict__ nv) {
    int i = threadIdx.x;   // 32 threads
    float A = 0.0f, Bv = 0.0f;
    if (i < C) {
        float cnt = 0.0f;
        #pragma unroll
        for (int b = 0; b < NB; ++b) cnt += (float)nv[b];
        float mean = g_stats[i] / cnt;
        float var  = g_stats[C + i] / cnt - mean * mean;
        A  = rsqrtf(var + EPSF) * gamma[i];
        Bv = beta[i] - mean * A;
    }
    __syncwarp();
    if (i < C) { g_affine[i] = A; g_affine[C + i] = Bv; }
    g_stats[i] = 0.0f;     // replay-safe: stats zeroed for next conv / next replay
}

// ---------------- final affine+relu+mask ----------------
__global__ __launch_bounds__(256)
void k_apply(const float* __restrict__ t, const int* __restrict__ nv,
             float* __restrict__ out) {
    __shared__ float sA[32];
    if (threadIdx.x < 32) sA[threadIdx.x] = g_affine[threadIdx.x];
    __syncthreads();
    int bn = blockIdx.x * 256 + threadIdx.x;
    int b = bn >> 16, n = bn & 0xFFFF;
    float4* po = reinterpret_cast<float4*>(out + (size_t)bn * C);
    if (n < nv[b]) {
        const float4* r = reinterpret_cast<const float4*>(t + (size_t)bn * C);
        #pragma unroll
        for (int k = 0; k < 4; ++k) {
            float4 v = r[k];
            float4 y;
            y.x = fmaxf(0.0f, v.x * sA[4*k+0] + sA[16+4*k+0]);
            y.y = fmaxf(0.0f, v.y * sA[4*k+1] + sA[16+4*k+1]);
            y.z = fmaxf(0.0f, v.z * sA[4*k+2] + sA[16+4*k+2]);
            y.w = fmaxf(0.0f, v.w * sA[4*k+3] + sA[16+4*k+3]);
            po[k] = y;
        }
    } else {
        float4 z = make_float4(0.f, 0.f, 0.f, 0.f);
        #pragma unroll
        for (int k = 0; k < 4; ++k) po[k] = z;
    }
}

// ---------------- launch ----------------
extern "C" void kernel_launch(void* const* d_in, const int* in_sizes, int n_in,
                              void* d_out, int out_size) {
    const float* feats = (const float*)d_in[0];
    const int*   xyz   = (const int*)  d_in[1];
    const int*   nv    = (const int*)  d_in[2];
    const float* w0    = (const float*)d_in[3];
    const float* w1    = (const float*)d_in[4];
    const float* nw0   = (const float*)d_in[5];
    const float* nw1   = (const float*)d_in[6];
    const float* ga0   = (const float*)d_in[7];
    const float* be0   = (const float*)d_in[8];
    const float* ga1   = (const float*)d_in[9];
    const float* be1   = (const float*)d_in[10];
    float* out = (float*)d_out;

    float *t0, *t1, *aff;
    cudaGetSymbolAddress((void**)&t0,  g_t0);
    cudaGetSymbolAddress((void**)&t1,  g_t1);
    cudaGetSymbolAddress((void**)&aff, g_affine);

    cudaFuncSetAttribute(k_conv<false>, cudaFuncAttributeMaxDynamicSharedMemorySize, SM_BYTES);
    cudaFuncSetAttribute(k_conv<true>,  cudaFuncAttributeMaxDynamicSharedMemorySize, SM_BYTES);

    // launch index:                                    (ncu -s 5 -c 1 -> #5 = conv<true>)
    k_init_map<<<(NB*G3/4)/256, 256>>>();             // 0
    k_scatter <<<BNTOT/256, 256>>>(xyz, nv);          // 1
    k_build   <<<NTILES, 1024>>>(xyz, nv);            // 2

    // g_stats starts zeroed (BSS on first call, k_finalize re-zeroes thereafter)
    k_conv<false><<<NTILES, 256, SM_BYTES>>>(feats, w0, nw0, nullptr, t0);  // 3
    k_finalize<<<1, 32>>>(ga0, be0, nv);                                    // 4
    k_conv<true> <<<NTILES, 256, SM_BYTES>>>(t0, w1, nw1, aff, t1);         // 5
    k_finalize<<<1, 32>>>(ga1, be1, nv);                                    // 6
    k_apply<<<BNTOT/256, 256>>>(t1, nv, out);                               // 7
}